// round 11
// baseline (speedup 1.0000x reference)
#include <cuda_runtime.h>
#include <cuda_fp16.h>
#include <cstdint>
#include <cmath>

#define NTOK 8192
#define HDIM 2048
#define IDIM 8192
#define KSEL 2048
#define DELTA 1.25e-3f
#define BCAP 160

__device__ float g_gate[(size_t)NTOK * IDIM];
__device__ float g_v   [(size_t)NTOK * IDIM];
__device__ __half g_xs [2 * (size_t)NTOK * HDIM];   // x 2-split
__device__ __half g_wgs[(size_t)IDIM * HDIM];       // Wg h-plane
__device__ __half g_wus[(size_t)IDIM * HDIM];       // Wu h-plane
__device__ __half g_wds[(size_t)HDIM * IDIM];       // Wd h-plane
__device__ __half g_as [2 * (size_t)NTOK * IDIM];   // act 2-split

__device__ __forceinline__ uint32_t smem_u32(const void* p) {
    uint32_t a;
    asm("{ .reg .u64 t; cvta.to.shared.u64 t, %1; cvt.u32.u64 %0, t; }" : "=r"(a) : "l"(p));
    return a;
}
#define CP16(d, s)  asm volatile("cp.async.cg.shared.global [%0], [%1], 16;" :: "r"(d), "l"(s) : "memory")
#define CP_COMMIT() asm volatile("cp.async.commit_group;" ::: "memory")
#define CP_WAIT(n)  asm volatile("cp.async.wait_group %0;" :: "n"(n) : "memory")
#define LDM4(r0, r1, r2, r3, a) \
    asm volatile("ldmatrix.sync.aligned.m8n8.x4.shared.b16 {%0,%1,%2,%3}, [%4];" \
                 : "=r"(r0), "=r"(r1), "=r"(r2), "=r"(r3) : "r"(a))
#define MMA16816(c0, c1, c2, c3, a0, a1, a2, a3, b0, b1) \
    asm volatile("mma.sync.aligned.m16n8k16.row.col.f32.f16.f16.f32 " \
                 "{%0,%1,%2,%3},{%4,%5,%6,%7},{%8,%9},{%0,%1,%2,%3};" \
                 : "+f"(c0), "+f"(c1), "+f"(c2), "+f"(c3) \
                 : "r"(a0), "r"(a1), "r"(a2), "r"(a3), "r"(b0), "r"(b1))
#define SWZ(o) ((uint32_t)(o) ^ ((((uint32_t)(o)) >> 3) & 0x70u))

__device__ __forceinline__ unsigned f2k(float f) {
    unsigned b = __float_as_uint(f);
    return (b & 0x80000000u) ? ~b : (b | 0x80000000u);
}
__device__ __forceinline__ float k2f(unsigned u) {
    unsigned b = (u & 0x80000000u) ? (u & 0x7FFFFFFFu) : ~u;
    return __uint_as_float(b);
}

// ---------------------------------------------------------------------------
// Shared-plane split-fp16 GEMM (R9-proven).  C = alpha * sum_p A[pa]·B[pb]^T
// CTA 128x256, 256 thr, warp tile 64x64, K-chunk 64, cp.async pipeline.
// ---------------------------------------------------------------------------
#define BM 128
#define BN 256

template<int SA, int SB>
__device__ __forceinline__ void hload(uint32_t st,
    const __half* __restrict__ A, const __half* __restrict__ B,
    int bm, int bn, int K, size_t plA, size_t plB, int k0, int tid)
{
#pragma unroll
    for (int p = 0; p < SA; p++) {
        const __half* Ab = A + (size_t)p * plA + k0;
#pragma unroll
        for (int i = 0; i < 4; i++) {
            int idx = tid + i * 256;
            int r = idx >> 3, c8 = idx & 7;
            CP16(st + (uint32_t)p * 16384u + SWZ(r * 128 + c8 * 16),
                 Ab + (size_t)(bm + r) * K + c8 * 8);
        }
    }
#pragma unroll
    for (int q = 0; q < SB; q++) {
        const __half* Bb = B + (size_t)q * plB + k0;
#pragma unroll
        for (int i = 0; i < 8; i++) {
            int idx = tid + i * 256;
            int r = idx >> 3, c8 = idx & 7;
            CP16(st + (uint32_t)(SA * 16384) + (uint32_t)q * 32768u + SWZ(r * 128 + c8 * 16),
                 Bb + (size_t)(bn + r) * K + c8 * 8);
        }
    }
    CP_COMMIT();
}

template<int SA, int SB, int NP, int NSTG, int PA, int PB>
__global__ __launch_bounds__(256, 1)
void hgemm(const __half* __restrict__ A, const __half* __restrict__ B,
           float* __restrict__ C, int N, int K, size_t plA, size_t plB, float alpha)
{
    constexpr int STAGE = SA * 16384 + SB * 32768;
    extern __shared__ char smem[];
    const uint32_t sb = smem_u32(smem);
    const int tid = threadIdx.x, wid = tid >> 5, lane = tid & 31;
    const int bm = blockIdx.y * BM, bn = blockIdx.x * BN;
    const int wm = (wid >> 2) * 64, wn = (wid & 3) * 64;
    const int CH = K >> 6;

    float c[4][8][4];
#pragma unroll
    for (int i = 0; i < 4; i++)
#pragma unroll
        for (int j = 0; j < 8; j++)
#pragma unroll
            for (int q = 0; q < 4; q++) c[i][j][q] = 0.f;

#pragma unroll
    for (int s = 0; s < NSTG - 1; s++)
        hload<SA, SB>(sb + (uint32_t)s * STAGE, A, B, bm, bn, K, plA, plB, s * 64, tid);

    const int a_mrow = lane & 15;
    const int a_kc   = lane >> 4;
    const int b_nrow = (lane & 7) + ((lane >> 4) << 3);
    const int b_kc   = (lane >> 3) & 1;

    for (int t = 0; t < CH; t++) {
        const uint32_t st = sb + (uint32_t)(t % NSTG) * STAGE;
        CP_WAIT(NSTG - 2);
        __syncthreads();
        if (t + NSTG - 1 < CH)
            hload<SA, SB>(sb + (uint32_t)((t + NSTG - 1) % NSTG) * STAGE, A, B,
                          bm, bn, K, plA, plB, (t + NSTG - 1) * 64, tid);
        else
            CP_COMMIT();

#pragma unroll
        for (int kk = 0; kk < 4; kk++) {
            uint32_t a[SA][4][4], b[SB][4][4];
#pragma unroll
            for (int p = 0; p < SA; p++)
#pragma unroll
                for (int mt = 0; mt < 4; mt++) {
                    int r = wm + mt * 16 + a_mrow;
                    int ch = kk * 2 + a_kc;
                    LDM4(a[p][mt][0], a[p][mt][1], a[p][mt][2], a[p][mt][3],
                         st + (uint32_t)p * 16384u + SWZ(r * 128 + ch * 16));
                }
#pragma unroll
            for (int q = 0; q < SB; q++)
#pragma unroll
                for (int nt = 0; nt < 4; nt++) {
                    int r = wn + nt * 16 + b_nrow;
                    int ch = kk * 2 + b_kc;
                    LDM4(b[q][nt][0], b[q][nt][1], b[q][nt][2], b[q][nt][3],
                         st + (uint32_t)(SA * 16384) + (uint32_t)q * 32768u + SWZ(r * 128 + ch * 16));
                }
#pragma unroll
            for (int p = 0; p < NP; p++) {
                const int pa = (PA >> (4 * p)) & 15;
                const int pb = (PB >> (4 * p)) & 15;
#pragma unroll
                for (int mt = 0; mt < 4; mt++)
#pragma unroll
                    for (int j = 0; j < 8; j++)
                        MMA16816(c[mt][j][0], c[mt][j][1], c[mt][j][2], c[mt][j][3],
                                 a[pa][mt][0], a[pa][mt][1], a[pa][mt][2], a[pa][mt][3],
                                 b[pb][j >> 1][(j & 1) * 2], b[pb][j >> 1][(j & 1) * 2 + 1]);
            }
        }
    }

#pragma unroll
    for (int mt = 0; mt < 4; mt++) {
        int row = bm + wm + mt * 16 + (lane >> 2);
#pragma unroll
        for (int j = 0; j < 8; j++) {
            int col = bn + wn + j * 8 + (lane & 3) * 2;
            *(float2*)(C + (size_t)row * N + col) =
                make_float2(alpha * c[mt][j][0], alpha * c[mt][j][1]);
            *(float2*)(C + (size_t)(row + 8) * N + col) =
                make_float2(alpha * c[mt][j][2], alpha * c[mt][j][3]);
        }
    }
}

// ---------------------------------------------------------------------------
__global__ void split2h(const float4* __restrict__ a, __half* __restrict__ o, size_t n)
{
    const size_t n4 = n >> 2;
    size_t i = (size_t)blockIdx.x * blockDim.x + threadIdx.x;
    for (; i < n4; i += (size_t)gridDim.x * blockDim.x) {
        float4 x = a[i];
        __half h0 = __float2half_rn(x.x), h1 = __float2half_rn(x.y);
        __half h2 = __float2half_rn(x.z), h3 = __float2half_rn(x.w);
        *(__half2*)(o + 4 * i)     = __halves2half2(h0, h1);
        *(__half2*)(o + 4 * i + 2) = __halves2half2(h2, h3);
        *(__half2*)(o + n + 4 * i) = __halves2half2(
            __float2half_rn(x.x - __half2float(h0)), __float2half_rn(x.y - __half2float(h1)));
        *(__half2*)(o + n + 4 * i + 2) = __halves2half2(
            __float2half_rn(x.z - __half2float(h2)), __float2half_rn(x.w - __half2float(h3)));
    }
}
__global__ void split1h(const float4* __restrict__ a, __half* __restrict__ o, size_t n)
{
    const size_t n4 = n >> 2;
    size_t i = (size_t)blockIdx.x * blockDim.x + threadIdx.x;
    for (; i < n4; i += (size_t)gridDim.x * blockDim.x) {
        float4 x = a[i];
        *(__half2*)(o + 4 * i)     = __halves2half2(__float2half_rn(x.x), __float2half_rn(x.y));
        *(__half2*)(o + 4 * i + 2) = __halves2half2(__float2half_rn(x.z), __float2half_rn(x.w));
    }
}

// ---------------------------------------------------------------------------
// Top-K with exact boundary resolution:
//  1. radix-select threshold on the (approximate) MMA gate
//  2. channels > thr+DELTA: definitely selected
//  3. channels within +-DELTA: recompute gate in fp32 sequential-k order
//     (matches reference rounding; proven by R1's 8.5e-7) and rank exactly
//  4. fuse silu(gate)*v, emit fp16 2-way split
// ---------------------------------------------------------------------------
__global__ __launch_bounds__(256)
void topk_kernel(const float* __restrict__ gate, const float* __restrict__ v,
                 const float* __restrict__ x, const float* __restrict__ Wg,
                 __half* __restrict__ ah, __half* __restrict__ am)
{
    __shared__ unsigned s_u[IDIM];       // 32 KB
    __shared__ float    s_x[HDIM];       // 8 KB
    __shared__ int      hist[256];
    __shared__ int      s_bidx[BCAP];
    __shared__ float    s_bg[BCAP];
    __shared__ unsigned char s_bsel[BCAP];
    __shared__ unsigned s_prefix;
    __shared__ int s_kk, s_na, s_nb;

    const int row = blockIdx.x, tid = threadIdx.x;
    const float* grow = gate + (size_t)row * IDIM;
    const float* vrow = v + (size_t)row * IDIM;
    const float* xrow = x + (size_t)row * HDIM;

    for (int i = tid * 4; i < IDIM; i += 1024) {
        float4 g4 = *(const float4*)(grow + i);
        s_u[i]     = f2k(g4.x); s_u[i + 1] = f2k(g4.y);
        s_u[i + 2] = f2k(g4.z); s_u[i + 3] = f2k(g4.w);
    }
    for (int k = tid * 4; k < HDIM; k += 1024)
        *(float4*)(s_x + k) = *(const float4*)(xrow + k);
    if (tid == 0) { s_prefix = 0u; s_kk = KSEL; s_na = 0; s_nb = 0; }
    __syncthreads();

#pragma unroll
    for (int pass = 0; pass < 4; pass++) {
        const int shift = 24 - 8 * pass;
        hist[tid] = 0;
        __syncthreads();
        const unsigned prefix = s_prefix;
        const unsigned himask = (pass == 0) ? 0u : (0xFFFFFFFFu << (shift + 8));
        for (int i = tid; i < IDIM; i += 256) {
            unsigned u = s_u[i];
            if ((u & himask) == prefix) atomicAdd(&hist[(u >> shift) & 255], 1);
        }
        __syncthreads();
        if (tid == 0) {
            int kk = s_kk, cum = 0, b = 0;
            for (int q = 255; q >= 0; q--) { cum += hist[q]; if (cum >= kk) { b = q; break; } }
            s_kk = kk - (cum - hist[b]);
            s_prefix = prefix | ((unsigned)b << shift);
        }
        __syncthreads();
    }
    const unsigned t = s_prefix;
    const float gt = k2f(t);
    const unsigned hik = f2k(gt + DELTA);
    const unsigned lok = f2k(gt - DELTA);
    __syncthreads();

    // Classify: count definite-selects, collect band members
    for (int i = tid; i < IDIM; i += 256) {
        unsigned u = s_u[i];
        if (u > hik) atomicAdd(&s_na, 1);
        else if (u >= lok) {
            int p = atomicAdd(&s_nb, 1);
            if (p < BCAP) s_bidx[p] = i;
        }
    }
    __syncthreads();
    const int nb = s_nb;
    const int nb_c = nb < BCAP ? nb : BCAP;
    const bool ovf = nb > BCAP;
    const int quota = KSEL - s_na;

    // Exact recompute for band members (sequential k, fp32 fmaf — matches ref)
    if (!ovf && tid < nb_c) {
        const float* wrow = Wg + (size_t)s_bidx[tid] * HDIM;
        float acc = 0.f;
#pragma unroll 8
        for (int k = 0; k < HDIM; k++) acc = fmaf(s_x[k], __ldg(wrow + k), acc);
        s_bg[tid] = acc;
    }
    __syncthreads();
    // Rank band on recomputed gates (ties: lower index first, as lax.top_k)
    if (!ovf && tid < nb_c) {
        const float gi = s_bg[tid];
        const int ii = s_bidx[tid];
        int r = 0;
        for (int j = 0; j < nb_c; j++) {
            float gj = s_bg[j];
            if (gj > gi || (gj == gi && s_bidx[j] < ii)) r++;
        }
        s_bsel[tid] = (r < quota) ? 1 : 0;
    }
    __syncthreads();

    for (int i = tid * 4; i < IDIM; i += 1024) {
        float4 v4 = *(const float4*)(vrow + i);
        __half hs[4], ms[4];
#pragma unroll
        for (int q = 0; q < 4; q++) {
            const unsigned u = s_u[i + q];
            float o = 0.f;
            if (u > hik) {
                float g = k2f(u);
                o = (g / (1.f + expf(-g))) * ((const float*)&v4)[q];
            } else if (u >= lok) {
                if (!ovf) {
                    for (int j = 0; j < nb_c; j++)
                        if (s_bidx[j] == i + q) {
                            if (s_bsel[j]) {
                                float g = s_bg[j];
                                o = (g / (1.f + expf(-g))) * ((const float*)&v4)[q];
                            }
                            break;
                        }
                } else if (u >= t) {   // pathological fallback (never expected)
                    float g = k2f(u);
                    o = (g / (1.f + expf(-g))) * ((const float*)&v4)[q];
                }
            }
            hs[q] = __float2half_rn(o);
            ms[q] = __float2half_rn(o - __half2float(hs[q]));
        }
        const size_t idx = (size_t)row * IDIM + i;
        *(__half2*)(ah + idx)     = __halves2half2(hs[0], hs[1]);
        *(__half2*)(ah + idx + 2) = __halves2half2(hs[2], hs[3]);
        *(__half2*)(am + idx)     = __halves2half2(ms[0], ms[1]);
        *(__half2*)(am + idx + 2) = __halves2half2(ms[2], ms[3]);
    }
}

// ---------------------------------------------------------------------------
extern "C" void kernel_launch(void* const* d_in, const int* in_sizes, int n_in,
                              void* d_out, int out_size)
{
    const float* x  = (const float*)d_in[0];
    const float* Wg = (const float*)d_in[1];
    const float* Wu = (const float*)d_in[2];
    const float* Wd = (const float*)d_in[3];
    float* out = (float*)d_out;

    float *gate, *vv;
    __half *xs, *wgs, *wus, *wds, *as;
    cudaGetSymbolAddress((void**)&gate, g_gate);
    cudaGetSymbolAddress((void**)&vv, g_v);
    cudaGetSymbolAddress((void**)&xs, g_xs);
    cudaGetSymbolAddress((void**)&wgs, g_wgs);
    cudaGetSymbolAddress((void**)&wus, g_wus);
    cudaGetSymbolAddress((void**)&wds, g_wds);
    cudaGetSymbolAddress((void**)&as, g_as);

    const size_t nx = (size_t)NTOK * HDIM;
    const size_t nw = (size_t)IDIM * HDIM;
    const size_t na = (size_t)NTOK * IDIM;

    // One GEMM shape for all three: (A_h + A_m) @ B_h^T, stage 64KB, 3 stages
    auto ks = hgemm<2, 1, 2, 3, 0x10, 0x00>;
    cudaFuncSetAttribute(ks, cudaFuncAttributeMaxDynamicSharedMemorySize, 196608);

    split2h<<<2048, 256>>>((const float4*)x,  xs,  nx);
    split1h<<<2048, 256>>>((const float4*)Wg, wgs, nw);
    split1h<<<2048, 256>>>((const float4*)Wu, wus, nw);
    split1h<<<2048, 256>>>((const float4*)Wd, wds, nw);

    // gate = x @ Wg^T (approximate; boundary fixed in topk)
    ks<<<dim3(IDIM / BN, NTOK / BM), 256, 196608>>>(
        xs, wgs, gate, IDIM, HDIM, nx, nw, 1.0f);
    // v = x @ Wu^T
    ks<<<dim3(IDIM / BN, NTOK / BM), 256, 196608>>>(
        xs, wus, vv, IDIM, HDIM, nx, nw, 1.0f);
    // exact-boundary top-k + silu*v -> fp16 2-split activation
    topk_kernel<<<NTOK, 256>>>(gate, vv, x, Wg, as, as + na);
    // out = act @ Wd^T
    ks<<<dim3(HDIM / BN, NTOK / BM), 256, 196608>>>(
        as, wds, out, HDIM, IDIM, na, nw, 1.0f);
}

// round 12
// speedup vs baseline: 1.1582x; 1.1582x over previous
#include <cuda_runtime.h>
#include <cuda_fp16.h>
#include <cstdint>
#include <cmath>

#define NTOK 8192
#define HDIM 2048
#define IDIM 8192
#define KSEL 2048
#define DELTA 1.25e-3f
#define BCAP 160

__device__ float g_gate[(size_t)NTOK * IDIM];
__device__ float g_v   [(size_t)NTOK * IDIM];
__device__ __half g_xs [2 * (size_t)NTOK * HDIM];   // x 2-split
__device__ __half g_wgs[(size_t)IDIM * HDIM];       // Wg h-plane
__device__ __half g_wus[(size_t)IDIM * HDIM];       // Wu h-plane
__device__ __half g_wds[(size_t)HDIM * IDIM];       // Wd h-plane
__device__ __half g_as [2 * (size_t)NTOK * IDIM];   // act 2-split

__device__ __forceinline__ uint32_t smem_u32(const void* p) {
    uint32_t a;
    asm("{ .reg .u64 t; cvta.to.shared.u64 t, %1; cvt.u32.u64 %0, t; }" : "=r"(a) : "l"(p));
    return a;
}
#define CP16(d, s)  asm volatile("cp.async.cg.shared.global [%0], [%1], 16;" :: "r"(d), "l"(s) : "memory")
#define CP_COMMIT() asm volatile("cp.async.commit_group;" ::: "memory")
#define CP_WAIT(n)  asm volatile("cp.async.wait_group %0;" :: "n"(n) : "memory")
#define LDM4(r0, r1, r2, r3, a) \
    asm volatile("ldmatrix.sync.aligned.m8n8.x4.shared.b16 {%0,%1,%2,%3}, [%4];" \
                 : "=r"(r0), "=r"(r1), "=r"(r2), "=r"(r3) : "r"(a))
#define MMA16816(c0, c1, c2, c3, a0, a1, a2, a3, b0, b1) \
    asm volatile("mma.sync.aligned.m16n8k16.row.col.f32.f16.f16.f32 " \
                 "{%0,%1,%2,%3},{%4,%5,%6,%7},{%8,%9},{%0,%1,%2,%3};" \
                 : "+f"(c0), "+f"(c1), "+f"(c2), "+f"(c3) \
                 : "r"(a0), "r"(a1), "r"(a2), "r"(a3), "r"(b0), "r"(b1))
#define SWZ(o) ((uint32_t)(o) ^ ((((uint32_t)(o)) >> 3) & 0x70u))

__device__ __forceinline__ unsigned f2k(float f) {
    unsigned b = __float_as_uint(f);
    return (b & 0x80000000u) ? ~b : (b | 0x80000000u);
}
__device__ __forceinline__ float k2f(unsigned u) {
    unsigned b = (u & 0x80000000u) ? (u & 0x7FFFFFFFu) : ~u;
    return __uint_as_float(b);
}

// ---------------------------------------------------------------------------
// Shared-plane split-fp16 GEMM.  C = alpha * sum_p A[pa]·B[pb]^T
// CTA 128x256, 256 thr, warp tile 64x64, K-chunk 64, cp.async pipeline.
// ---------------------------------------------------------------------------
#define BM 128
#define BN 256

template<int SA, int SB>
__device__ __forceinline__ void hload(uint32_t st,
    const __half* __restrict__ A, const __half* __restrict__ B,
    int bm, int bn, int K, size_t plA, size_t plB, int k0, int tid)
{
#pragma unroll
    for (int p = 0; p < SA; p++) {
        const __half* Ab = A + (size_t)p * plA + k0;
#pragma unroll
        for (int i = 0; i < 4; i++) {
            int idx = tid + i * 256;
            int r = idx >> 3, c8 = idx & 7;
            CP16(st + (uint32_t)p * 16384u + SWZ(r * 128 + c8 * 16),
                 Ab + (size_t)(bm + r) * K + c8 * 8);
        }
    }
#pragma unroll
    for (int q = 0; q < SB; q++) {
        const __half* Bb = B + (size_t)q * plB + k0;
#pragma unroll
        for (int i = 0; i < 8; i++) {
            int idx = tid + i * 256;
            int r = idx >> 3, c8 = idx & 7;
            CP16(st + (uint32_t)(SA * 16384) + (uint32_t)q * 32768u + SWZ(r * 128 + c8 * 16),
                 Bb + (size_t)(bn + r) * K + c8 * 8);
        }
    }
    CP_COMMIT();
}

template<int SA, int SB, int NP, int NSTG, int PA, int PB>
__global__ __launch_bounds__(256, 1)
void hgemm(const __half* __restrict__ A, const __half* __restrict__ B,
           float* __restrict__ C, int N, int K, size_t plA, size_t plB, float alpha)
{
    constexpr int STAGE = SA * 16384 + SB * 32768;
    extern __shared__ char smem[];
    const uint32_t sb = smem_u32(smem);
    const int tid = threadIdx.x, wid = tid >> 5, lane = tid & 31;
    const int bm = blockIdx.y * BM, bn = blockIdx.x * BN;
    const int wm = (wid >> 2) * 64, wn = (wid & 3) * 64;
    const int CH = K >> 6;

    float c[4][8][4];
#pragma unroll
    for (int i = 0; i < 4; i++)
#pragma unroll
        for (int j = 0; j < 8; j++)
#pragma unroll
            for (int q = 0; q < 4; q++) c[i][j][q] = 0.f;

#pragma unroll
    for (int s = 0; s < NSTG - 1; s++)
        hload<SA, SB>(sb + (uint32_t)s * STAGE, A, B, bm, bn, K, plA, plB, s * 64, tid);

    const int a_mrow = lane & 15;
    const int a_kc   = lane >> 4;
    const int b_nrow = (lane & 7) + ((lane >> 4) << 3);
    const int b_kc   = (lane >> 3) & 1;

    for (int t = 0; t < CH; t++) {
        const uint32_t st = sb + (uint32_t)(t % NSTG) * STAGE;
        CP_WAIT(NSTG - 2);
        __syncthreads();
        if (t + NSTG - 1 < CH)
            hload<SA, SB>(sb + (uint32_t)((t + NSTG - 1) % NSTG) * STAGE, A, B,
                          bm, bn, K, plA, plB, (t + NSTG - 1) * 64, tid);
        else
            CP_COMMIT();

#pragma unroll
        for (int kk = 0; kk < 4; kk++) {
            uint32_t a[SA][4][4], b[SB][4][4];
#pragma unroll
            for (int q = 0; q < SB; q++)
#pragma unroll
                for (int nt = 0; nt < 4; nt++) {
                    int r = wn + nt * 16 + b_nrow;
                    int ch = kk * 2 + b_kc;
                    LDM4(b[q][nt][0], b[q][nt][1], b[q][nt][2], b[q][nt][3],
                         st + (uint32_t)(SA * 16384) + (uint32_t)q * 32768u + SWZ(r * 128 + ch * 16));
                }
#pragma unroll
            for (int p = 0; p < SA; p++)
#pragma unroll
                for (int mt = 0; mt < 4; mt++) {
                    int r = wm + mt * 16 + a_mrow;
                    int ch = kk * 2 + a_kc;
                    LDM4(a[p][mt][0], a[p][mt][1], a[p][mt][2], a[p][mt][3],
                         st + (uint32_t)p * 16384u + SWZ(r * 128 + ch * 16));
                }
#pragma unroll
            for (int p = 0; p < NP; p++) {
                const int pa = (PA >> (4 * p)) & 15;
                const int pb = (PB >> (4 * p)) & 15;
#pragma unroll
                for (int mt = 0; mt < 4; mt++)
#pragma unroll
                    for (int j = 0; j < 8; j++)
                        MMA16816(c[mt][j][0], c[mt][j][1], c[mt][j][2], c[mt][j][3],
                                 a[pa][mt][0], a[pa][mt][1], a[pa][mt][2], a[pa][mt][3],
                                 b[pb][j >> 1][(j & 1) * 2], b[pb][j >> 1][(j & 1) * 2 + 1]);
            }
        }
    }

#pragma unroll
    for (int mt = 0; mt < 4; mt++) {
        int row = bm + wm + mt * 16 + (lane >> 2);
#pragma unroll
        for (int j = 0; j < 8; j++) {
            int col = bn + wn + j * 8 + (lane & 3) * 2;
            *(float2*)(C + (size_t)row * N + col) =
                make_float2(alpha * c[mt][j][0], alpha * c[mt][j][1]);
            *(float2*)(C + (size_t)(row + 8) * N + col) =
                make_float2(alpha * c[mt][j][2], alpha * c[mt][j][3]);
        }
    }
}

// ---------------------------------------------------------------------------
__global__ void split2h(const float4* __restrict__ a, __half* __restrict__ o, size_t n)
{
    const size_t n4 = n >> 2;
    size_t i = (size_t)blockIdx.x * blockDim.x + threadIdx.x;
    for (; i < n4; i += (size_t)gridDim.x * blockDim.x) {
        float4 x = a[i];
        __half h0 = __float2half_rn(x.x), h1 = __float2half_rn(x.y);
        __half h2 = __float2half_rn(x.z), h3 = __float2half_rn(x.w);
        *(__half2*)(o + 4 * i)     = __halves2half2(h0, h1);
        *(__half2*)(o + 4 * i + 2) = __halves2half2(h2, h3);
        *(__half2*)(o + n + 4 * i) = __halves2half2(
            __float2half_rn(x.x - __half2float(h0)), __float2half_rn(x.y - __half2float(h1)));
        *(__half2*)(o + n + 4 * i + 2) = __halves2half2(
            __float2half_rn(x.z - __half2float(h2)), __float2half_rn(x.w - __half2float(h3)));
    }
}
__global__ void split1h(const float4* __restrict__ a, __half* __restrict__ o, size_t n)
{
    const size_t n4 = n >> 2;
    size_t i = (size_t)blockIdx.x * blockDim.x + threadIdx.x;
    for (; i < n4; i += (size_t)gridDim.x * blockDim.x) {
        float4 x = a[i];
        *(__half2*)(o + 4 * i)     = __halves2half2(__float2half_rn(x.x), __float2half_rn(x.y));
        *(__half2*)(o + 4 * i + 2) = __halves2half2(__float2half_rn(x.z), __float2half_rn(x.w));
    }
}

// ---------------------------------------------------------------------------
// Top-K with exact boundary resolution (staged cooperative recompute).
// ---------------------------------------------------------------------------
#define GRP 8
#define CHK 256

__global__ __launch_bounds__(256)
void topk_kernel(const float* __restrict__ gate, const float* __restrict__ v,
                 const float* __restrict__ x, const float* __restrict__ Wg,
                 __half* __restrict__ ah, __half* __restrict__ am)
{
    __shared__ unsigned s_u[IDIM];            // 32 KB
    __shared__ float    s_buf[GRP][CHK + 4];  // 8.1 KB  (band W rows, chunk)
    __shared__ float    s_xc[CHK];            // 1 KB    (x chunk)
    __shared__ int      hist[256];
    __shared__ int      s_bidx[BCAP];
    __shared__ float    s_bg[BCAP];
    __shared__ unsigned char s_bsel[BCAP];
    __shared__ unsigned s_prefix;
    __shared__ int s_kk, s_na, s_nb;

    const int row = blockIdx.x, tid = threadIdx.x;
    const float* grow = gate + (size_t)row * IDIM;
    const float* vrow = v + (size_t)row * IDIM;
    const float* xrow = x + (size_t)row * HDIM;

    for (int i = tid * 4; i < IDIM; i += 1024) {
        float4 g4 = *(const float4*)(grow + i);
        s_u[i]     = f2k(g4.x); s_u[i + 1] = f2k(g4.y);
        s_u[i + 2] = f2k(g4.z); s_u[i + 3] = f2k(g4.w);
    }
    if (tid == 0) { s_prefix = 0u; s_kk = KSEL; s_na = 0; s_nb = 0; }
    __syncthreads();

#pragma unroll
    for (int pass = 0; pass < 4; pass++) {
        const int shift = 24 - 8 * pass;
        hist[tid] = 0;
        __syncthreads();
        const unsigned prefix = s_prefix;
        const unsigned himask = (pass == 0) ? 0u : (0xFFFFFFFFu << (shift + 8));
        for (int i = tid; i < IDIM; i += 256) {
            unsigned u = s_u[i];
            if ((u & himask) == prefix) atomicAdd(&hist[(u >> shift) & 255], 1);
        }
        __syncthreads();
        if (tid == 0) {
            int kk = s_kk, cum = 0, b = 0;
            for (int q = 255; q >= 0; q--) { cum += hist[q]; if (cum >= kk) { b = q; break; } }
            s_kk = kk - (cum - hist[b]);
            s_prefix = prefix | ((unsigned)b << shift);
        }
        __syncthreads();
    }
    const unsigned t = s_prefix;
    const float gt = k2f(t);
    const unsigned hik = f2k(gt + DELTA);
    const unsigned lok = f2k(gt - DELTA);
    __syncthreads();

    // Classify channels
    for (int i = tid; i < IDIM; i += 256) {
        unsigned u = s_u[i];
        if (u > hik) atomicAdd(&s_na, 1);
        else if (u >= lok) {
            int p = atomicAdd(&s_nb, 1);
            if (p < BCAP) s_bidx[p] = i;
        }
    }
    __syncthreads();
    const int nb = s_nb;
    const int nb_c = nb < BCAP ? nb : BCAP;
    const bool ovf = nb > BCAP;
    const int quota = KSEL - s_na;

    // Staged cooperative exact recompute: groups of GRP band rows, k-chunks of
    // CHK. Loads are coalesced; accumulation stays strictly sequential in k
    // per element (the rounding order that matches the reference, per R1).
    if (!ovf) {
        for (int g0 = 0; g0 < nb_c; g0 += GRP) {
            const int ng = min(GRP, nb_c - g0);
            float accR = 0.f;
            for (int c0 = 0; c0 < HDIM; c0 += CHK) {
                if (tid < CHK / 4)
                    *(float4*)(s_xc + tid * 4) = *(const float4*)(xrow + c0 + tid * 4);
#pragma unroll
                for (int q = 0; q < (GRP * CHK / 4) / 256; q++) {
                    int idx = tid + q * 256;
                    int e = idx / (CHK / 4);
                    int f = idx % (CHK / 4);
                    if (e < ng)
                        *(float4*)(&s_buf[e][f * 4]) =
                            *(const float4*)(Wg + (size_t)s_bidx[g0 + e] * HDIM + c0 + f * 4);
                }
                __syncthreads();
                if (tid < ng) {
                    const float* bw = s_buf[tid];
#pragma unroll 8
                    for (int kk = 0; kk < CHK; kk++)
                        accR = fmaf(s_xc[kk], bw[kk], accR);
                }
                __syncthreads();
            }
            if (tid < ng) s_bg[g0 + tid] = accR;
        }
        __syncthreads();
        // Rank band on recomputed gates (ties: lower index first, per top_k)
        if (tid < nb_c) {
            const float gi = s_bg[tid];
            const int ii = s_bidx[tid];
            int r = 0;
            for (int j = 0; j < nb_c; j++) {
                float gj = s_bg[j];
                if (gj > gi || (gj == gi && s_bidx[j] < ii)) r++;
            }
            s_bsel[tid] = (r < quota) ? 1 : 0;
        }
        __syncthreads();
    }

    for (int i = tid * 4; i < IDIM; i += 1024) {
        float4 v4 = *(const float4*)(vrow + i);
        __half hs[4], ms[4];
#pragma unroll
        for (int q = 0; q < 4; q++) {
            const unsigned u = s_u[i + q];
            float o = 0.f;
            if (u > hik) {
                float g = k2f(u);
                o = (g / (1.f + expf(-g))) * ((const float*)&v4)[q];
            } else if (u >= lok) {
                if (!ovf) {
                    for (int j = 0; j < nb_c; j++)
                        if (s_bidx[j] == i + q) {
                            if (s_bsel[j]) {
                                float g = s_bg[j];
                                o = (g / (1.f + expf(-g))) * ((const float*)&v4)[q];
                            }
                            break;
                        }
                } else if (u >= t) {   // pathological fallback
                    float g = k2f(u);
                    o = (g / (1.f + expf(-g))) * ((const float*)&v4)[q];
                }
            }
            hs[q] = __float2half_rn(o);
            ms[q] = __float2half_rn(o - __half2float(hs[q]));
        }
        const size_t idx = (size_t)row * IDIM + i;
        *(__half2*)(ah + idx)     = __halves2half2(hs[0], hs[1]);
        *(__half2*)(ah + idx + 2) = __halves2half2(hs[2], hs[3]);
        *(__half2*)(am + idx)     = __halves2half2(ms[0], ms[1]);
        *(__half2*)(am + idx + 2) = __halves2half2(ms[2], ms[3]);
    }
}

// ---------------------------------------------------------------------------
extern "C" void kernel_launch(void* const* d_in, const int* in_sizes, int n_in,
                              void* d_out, int out_size)
{
    const float* x  = (const float*)d_in[0];
    const float* Wg = (const float*)d_in[1];
    const float* Wu = (const float*)d_in[2];
    const float* Wd = (const float*)d_in[3];
    float* out = (float*)d_out;

    float *gate, *vv;
    __half *xs, *wgs, *wus, *wds, *as;
    cudaGetSymbolAddress((void**)&gate, g_gate);
    cudaGetSymbolAddress((void**)&vv, g_v);
    cudaGetSymbolAddress((void**)&xs, g_xs);
    cudaGetSymbolAddress((void**)&wgs, g_wgs);
    cudaGetSymbolAddress((void**)&wus, g_wus);
    cudaGetSymbolAddress((void**)&wds, g_wds);
    cudaGetSymbolAddress((void**)&as, g_as);

    const size_t nx = (size_t)NTOK * HDIM;
    const size_t nw = (size_t)IDIM * HDIM;
    const size_t na = (size_t)NTOK * IDIM;

    auto ks = hgemm<2, 1, 2, 3, 0x10, 0x00>;
    cudaFuncSetAttribute(ks, cudaFuncAttributeMaxDynamicSharedMemorySize, 196608);

    split2h<<<2048, 256>>>((const float4*)x,  xs,  nx);
    split1h<<<2048, 256>>>((const float4*)Wg, wgs, nw);
    split1h<<<2048, 256>>>((const float4*)Wu, wus, nw);
    split1h<<<2048, 256>>>((const float4*)Wd, wds, nw);

    // gate = x @ Wg^T (approximate; boundary fixed in topk)
    ks<<<dim3(IDIM / BN, NTOK / BM), 256, 196608>>>(
        xs, wgs, gate, IDIM, HDIM, nx, nw, 1.0f);
    // v = x @ Wu^T
    ks<<<dim3(IDIM / BN, NTOK / BM), 256, 196608>>>(
        xs, wus, vv, IDIM, HDIM, nx, nw, 1.0f);
    // exact-boundary top-k + silu*v -> fp16 2-split activation
    topk_kernel<<<NTOK, 256>>>(gate, vv, x, Wg, as, as + na);
    // out = act @ Wd^T
    ks<<<dim3(HDIM / BN, NTOK / BM), 256, 196608>>>(
        as, wds, out, HDIM, IDIM, na, nw, 1.0f);
}